// round 1
// baseline (speedup 1.0000x reference)
#include <cuda_runtime.h>
#include <math.h>

// Problem constants (T=2048, H=2048, HQ=32, HKV=2, D=64, G=16, M<=32)
#define TMAX 2048
#define NH   2048     // H
#define HQN  32
#define HKVN 2
#define GN   16
#define DN   64
#define MMAX 32

// ---------------- scratch (no allocation allowed) ----------------
__device__ float    g_q[TMAX * 2048];      // [n, HQ*D]
__device__ float    g_k[TMAX * 128];       // [n, HKV*D]
__device__ float    g_v[TMAX * 128];
__device__ float    g_gl[TMAX * 96];       // gate logits [n, HQ*3]
__device__ float    g_ck[MMAX * HKVN * DN];
__device__ float    g_cv[MMAX * HKVN * DN];
__device__ float    g_comp[TMAX * 2048];   // compressed branch output [n, HQ*D]
__device__ float    g_fused[TMAX * 2048];  // gated fusion [n, HQ*D]
__device__ unsigned g_sel[TMAX * HKVN];    // selected-block bitmask per (n, hkv)

// ---------------- generic fp32 tiled GEMM: C[M,N] = A[M,K] @ B[K,N] ----------------
// BM=BN=64, BK=16, 256 threads, 4x4 microtile. M%64==0, K%16==0 assumed; N guarded.
__global__ void __launch_bounds__(256) gemm_kernel(
    const float* __restrict__ A, const float* __restrict__ B, float* __restrict__ C,
    int M, int N, int K)
{
    __shared__ float As[16][64];
    __shared__ float Bs[16][64];
    const int tid = threadIdx.x;
    const int tx = tid & 15, ty = tid >> 4;
    const int row0 = blockIdx.y * 64;
    const int col0 = blockIdx.x * 64;
    float acc[4][4] = {};
    for (int k0 = 0; k0 < K; k0 += 16) {
#pragma unroll
        for (int i = 0; i < 4; i++) {
            int e = tid + i * 256;          // 64*16 = 1024 elems
            int m = e >> 4, kk = e & 15;
            As[kk][m] = A[(row0 + m) * K + (k0 + kk)];
        }
#pragma unroll
        for (int i = 0; i < 4; i++) {
            int e = tid + i * 256;
            int kk = e >> 6, nn = e & 63;
            int col = col0 + nn;
            Bs[kk][nn] = (col < N) ? B[(k0 + kk) * N + col] : 0.f;
        }
        __syncthreads();
#pragma unroll
        for (int kk = 0; kk < 16; kk++) {
            float a[4], b[4];
#pragma unroll
            for (int i = 0; i < 4; i++) a[i] = As[kk][ty * 4 + i];
#pragma unroll
            for (int j = 0; j < 4; j++) b[j] = Bs[kk][tx * 4 + j];
#pragma unroll
            for (int i = 0; i < 4; i++)
#pragma unroll
                for (int j = 0; j < 4; j++)
                    acc[i][j] = fmaf(a[i], b[j], acc[i][j]);
        }
        __syncthreads();
    }
#pragma unroll
    for (int i = 0; i < 4; i++) {
        int r = row0 + ty * 4 + i;
#pragma unroll
        for (int j = 0; j < 4; j++) {
            int c = col0 + tx * 4 + j;
            if (c < N) C[r * N + c] = acc[i][j];
        }
    }
}

// ---------------- compressed tokens: ck[m,h,d], cv[m,h,d] ----------------
// ck = sum_t (k[m*64+t,h,d] + pe[h,t,d]) * w_ck[h,t];  cv = sum_t v * w_cv
__global__ void compress_kernel(const float* __restrict__ wck,
                                const float* __restrict__ wcv,
                                const float* __restrict__ pe)
{
    const int m = blockIdx.x, h = blockIdx.y, d = threadIdx.x;  // 64 threads
    float a = 0.f, b = 0.f;
    for (int t = 0; t < 64; t++) {
        const float wk = wck[h * 64 + t];
        const float wv = wcv[h * 64 + t];
        const int row = m * 64 + t;
        a = fmaf(g_k[row * 128 + h * 64 + d] + pe[(h * 64 + t) * 64 + d], wk, a);
        b = fmaf(g_v[row * 128 + h * 64 + d], wv, b);
    }
    g_ck[(m * 2 + h) * 64 + d] = a;
    g_cv[(m * 2 + h) * 64 + d] = b;
}

// ---------------- compressed attention + inline top-k block selection ----------------
// grid (n, hkv), 128 threads. Produces g_comp and g_sel.
__global__ void __launch_bounds__(128) comp_attn_kernel(int ntok)
{
    const int n = blockIdx.x, h = blockIdx.y;
    const int tid = threadIdx.x;
    const int M = ntok >> 6;                 // 32 for T=2048
    __shared__ float sq[1024];               // [16][64]
    __shared__ float sck[MMAX * 64];
    __shared__ float scv[MMAX * 64];
    __shared__ float lg[16 * 32];            // logits -> probabilities
    __shared__ float ssum[32];

    for (int i = tid; i < 1024; i += 128) sq[i] = g_q[n * 2048 + h * 1024 + i];
    for (int i = tid; i < M * 64; i += 128) {
        int m = i >> 6, d = i & 63;
        sck[i] = g_ck[(m * 2 + h) * 64 + d];
        scv[i] = g_cv[(m * 2 + h) * 64 + d];
    }
    __syncthreads();

    // visible compressed tokens: m*64+63 <= n
    const int mvis = (n >= 63) ? (((n - 63) >> 6) + 1) : 0;

    for (int e = tid; e < 16 * M; e += 128) {
        int g = e / M, m = e - g * M;
        float a = 0.f;
#pragma unroll 16
        for (int d = 0; d < 64; d++) a = fmaf(sq[g * 64 + d], sck[m * 64 + d], a);
        lg[g * 32 + m] = a * 0.125f;         // 1/sqrt(64)
    }
    __syncthreads();

    if (tid < 16) {
        const int g = tid;
        if (mvis == 0) {
            for (int m = 0; m < M; m++) lg[g * 32 + m] = 0.f;   // masked row -> zeros
        } else {
            float mx = -INFINITY;
            for (int m = 0; m < mvis; m++) mx = fmaxf(mx, lg[g * 32 + m]);
            float s = 0.f;
            for (int m = 0; m < mvis; m++) {
                float p = __expf(lg[g * 32 + m] - mx);
                lg[g * 32 + m] = p; s += p;
            }
            const float inv = 1.f / s;
            for (int m = 0; m < mvis; m++) lg[g * 32 + m] *= inv;
            for (int m = mvis; m < M; m++) lg[g * 32 + m] = 0.f;
        }
    }
    __syncthreads();

    for (int e = tid; e < 1024; e += 128) {
        int g = e >> 6, d = e & 63;
        float a = 0.f;
        for (int m = 0; m < mvis; m++) a = fmaf(lg[g * 32 + m], scv[m * 64 + d], a);
        g_comp[n * 2048 + h * 1024 + e] = a;
    }

    if (tid < 32) {
        float s = 0.f;
        if (tid < M)
            for (int g = 0; g < 16; g++) s += lg[g * 32 + tid];
        ssum[tid] = s;
    }
    __syncthreads();

    if (tid == 0) {
        const int qblk = n >> 6;
        unsigned sel = 0;
        if (qblk + 1 <= 16) {
            sel = (1u << (qblk + 1)) - 1u;   // all valid blocks selected
        } else {
            float sc[32];
            for (int m = 0; m < 32; m++) {
                if (m > qblk)                               sc[m] = -INFINITY;
                else if (m == 0 || m == qblk || m == qblk - 1) sc[m] = INFINITY; // forced
                else                                        sc[m] = ssum[m];
            }
            // top-16, lowest index wins ties (matches jax.lax.top_k set semantics)
            for (int t = 0; t < 16; t++) {
                int best = 0; float bv = -INFINITY;
                for (int m = 0; m < 32; m++) {
                    if ((sel >> m) & 1u) continue;
                    if (sc[m] > bv) { bv = sc[m]; best = m; }
                }
                sel |= 1u << best;
            }
        }
        g_sel[n * 2 + h] = sel;
    }
}

// ---------------- main attention: sparse + window branches, fused gating ----------------
// grid (n, hkv), 256 threads. Flash-style over 64-key chunks; only active chunks visited.
__global__ void __launch_bounds__(256) main_attn_kernel(int ntok)
{
    const int n = blockIdx.x, h = blockIdx.y;
    const int tid = threadIdx.x;
    __shared__ float sq[1024];               // [16][64]
    __shared__ float sk[64 * 65];            // padded
    __shared__ float sv[64 * 64];
    __shared__ float lg[1024];               // logits, then p_sparse
    __shared__ float pw[1024];               // p_window
    __shared__ float hm[2][16], hl[2][16], hr[2][16];   // [branch][head]

    for (int i = tid; i < 1024; i += 256) sq[i] = g_q[n * 2048 + h * 1024 + i];
    if (tid < 32) { hm[tid >> 4][tid & 15] = -INFINITY; hl[tid >> 4][tid & 15] = 0.f; }
    float acc_s[4] = {0, 0, 0, 0}, acc_w[4] = {0, 0, 0, 0};

    const int qblk = n >> 6;
    const unsigned sel = g_sel[n * 2 + h];
    const int wlo = n - 512;                 // window: j >= wlo
    __syncthreads();

    for (int c = 0; c <= qblk; c++) {
        const bool as = (sel >> c) & 1u;
        const bool aw = (c * 64 + 63) >= wlo;
        if (!as && !aw) continue;
        const int jn = min(63, n - c * 64);  // causal bound within chunk

        for (int i = tid; i < 4096; i += 256) {
            int j = i >> 6, d = i & 63;
            bool ok = (j <= jn);
            int gi = (c * 64 + j) * 128 + h * 64 + d;
            sk[j * 65 + d] = ok ? g_k[gi] : 0.f;
            sv[j * 64 + d] = ok ? g_v[gi] : 0.f;
        }
        __syncthreads();

#pragma unroll
        for (int i = 0; i < 4; i++) {
            int e = tid + i * 256;
            int g = e >> 6, j = e & 63;
            float a = 0.f;
#pragma unroll 16
            for (int d = 0; d < 64; d++) a = fmaf(sq[g * 64 + d], sk[j * 65 + d], a);
            lg[e] = a * 0.125f;
        }
        __syncthreads();

        if (tid < 32) {
            const int br = tid >> 4, g = tid & 15;
            const bool act = br ? aw : as;
            float r = 1.f;
            if (act) {
                const int j0 = br ? max(0, wlo - c * 64) : 0;
                float cm = -INFINITY;
                for (int j = j0; j <= jn; j++) cm = fmaxf(cm, lg[g * 64 + j]);
                const float om = hm[br][g];
                const float nm = fmaxf(om, cm);
                r = __expf(om - nm);         // om == -inf -> 0
                hm[br][g] = nm;
            }
            hr[br][g] = r;
        }
        __syncthreads();

        const int jw0 = max(0, wlo - c * 64);
#pragma unroll
        for (int i = 0; i < 4; i++) {
            int e = tid + i * 256;
            int g = e >> 6, j = e & 63;
            const float l = lg[e];
            const bool jc = (j <= jn);
            lg[e] = (as && jc)             ? __expf(l - hm[0][g]) : 0.f;
            pw[e] = (aw && jc && j >= jw0) ? __expf(l - hm[1][g]) : 0.f;
        }
        __syncthreads();

        if (tid < 32) {
            const int br = tid >> 4, g = tid & 15;
            const float* pp = br ? pw : lg;
            float s = 0.f;
            for (int j = 0; j < 64; j++) s += pp[g * 64 + j];
            hl[br][g] = hl[br][g] * hr[br][g] + s;
        }
#pragma unroll
        for (int i = 0; i < 4; i++) {
            int e = tid + i * 256;
            int g = e >> 6, d = e & 63;
            float a_s = acc_s[i] * hr[0][g];
            float a_w = acc_w[i] * hr[1][g];
#pragma unroll 16
            for (int j = 0; j < 64; j++) {
                const float vv = sv[j * 64 + d];
                a_s = fmaf(lg[g * 64 + j], vv, a_s);
                a_w = fmaf(pw[g * 64 + j], vv, a_w);
            }
            acc_s[i] = a_s; acc_w[i] = a_w;
        }
        __syncthreads();
    }

    // gated fusion (self-key always valid in both branches -> hl > 0)
#pragma unroll
    for (int i = 0; i < 4; i++) {
        int e = tid + i * 256;
        int g = e >> 6;
        const int hq = h * 16 + g;
        const float gl0 = g_gl[n * 96 + hq * 3 + 0];
        const float gl1 = g_gl[n * 96 + hq * 3 + 1];
        const float gl2 = g_gl[n * 96 + hq * 3 + 2];
        const float g0 = 1.f / (1.f + __expf(-gl0));
        const float g1 = 1.f / (1.f + __expf(-gl1));
        const float g2 = 1.f / (1.f + __expf(-gl2));
        const float comp = g_comp[n * 2048 + h * 1024 + e];
        g_fused[n * 2048 + h * 1024 + e] =
            g0 * comp + g1 * (acc_s[i] / hl[0][g]) + g2 * (acc_w[i] / hl[1][g]);
    }
}

// ---------------- launch ----------------
extern "C" void kernel_launch(void* const* d_in, const int* in_sizes, int n_in,
                              void* d_out, int out_size)
{
    const float* x   = (const float*)d_in[0];
    // d_in[1] = cu_seqlens (single sequence; unused)
    const float* Wq  = (const float*)d_in[2];
    const float* Wk  = (const float*)d_in[3];
    const float* Wv  = (const float*)d_in[4];
    const float* Wo  = (const float*)d_in[5];
    const float* Wg  = (const float*)d_in[6];
    const float* wck = (const float*)d_in[7];
    const float* wcv = (const float*)d_in[8];
    const float* pe  = (const float*)d_in[9];
    float* out = (float*)d_out;

    const int ntok = in_sizes[0] / 2048;     // T
    const int M = ntok / 64;

    float *q, *k, *v, *gl, *fused;
    cudaGetSymbolAddress((void**)&q,     g_q);
    cudaGetSymbolAddress((void**)&k,     g_k);
    cudaGetSymbolAddress((void**)&v,     g_v);
    cudaGetSymbolAddress((void**)&gl,    g_gl);
    cudaGetSymbolAddress((void**)&fused, g_fused);

    gemm_kernel<<<dim3(2048 / 64, ntok / 64), 256>>>(x, Wq, q,  ntok, 2048, 2048);
    gemm_kernel<<<dim3(2,         ntok / 64), 256>>>(x, Wk, k,  ntok, 128,  2048);
    gemm_kernel<<<dim3(2,         ntok / 64), 256>>>(x, Wv, v,  ntok, 128,  2048);
    gemm_kernel<<<dim3(2,         ntok / 64), 256>>>(x, Wg, gl, ntok, 96,   2048);
    compress_kernel<<<dim3(M, 2), 64>>>(wck, wcv, pe);
    comp_attn_kernel<<<dim3(ntok, 2), 128>>>(ntok);
    main_attn_kernel<<<dim3(ntok, 2), 256>>>(ntok);
    gemm_kernel<<<dim3(2048 / 64, ntok / 64), 256>>>(fused, Wo, out, ntok, 2048, 2048);
}

// round 3
// speedup vs baseline: 1.4794x; 1.4794x over previous
#include <cuda_runtime.h>
#include <cuda_bf16.h>
#include <math.h>
#include <stdint.h>

// Problem constants (T=2048, H=2048, HQ=32, HKV=2, D=64, G=16, M<=32)
#define TMAX 2048
#define MMAX 32

// ---------------- scratch (no allocation allowed) ----------------
__device__ float    g_q[TMAX * 2048];      // [n, HQ*D]
__device__ float    g_kvg[TMAX * 352];     // [n, k(128) | v(128) | gate(96)]
__device__ float    g_ck[MMAX * 2 * 64];
__device__ float    g_cv[MMAX * 2 * 64];
__device__ float    g_comp[TMAX * 2048];
__device__ float    g_fused[TMAX * 2048];
__device__ unsigned g_sel[TMAX * 2];

// bf16 split operands for tensor-core GEMMs
__device__ __nv_bfloat16 g_xh[2048 * 2048], g_xl[2048 * 2048];
__device__ __nv_bfloat16 g_fh[2048 * 2048], g_fl[2048 * 2048];
__device__ __nv_bfloat16 g_wqt_h[2048 * 2048], g_wqt_l[2048 * 2048];   // Wq^T [N,K]
__device__ __nv_bfloat16 g_wot_h[2048 * 2048], g_wot_l[2048 * 2048];   // Wo^T
__device__ __nv_bfloat16 g_wkvgt_h[352 * 2048], g_wkvgt_l[352 * 2048]; // [Wk|Wv|Wg]^T

__device__ __forceinline__ uint32_t smem_u32(const void* p) {
    uint32_t a;
    asm("{ .reg .u64 t; cvta.to.shared.u64 t, %1; cvt.u32.u64 %0, t; }" : "=r"(a) : "l"(p));
    return a;
}

// ================= prep kernels =================
__global__ void split_fp32(const float* __restrict__ A,
                           __nv_bfloat16* __restrict__ Ah,
                           __nv_bfloat16* __restrict__ Al, int total)
{
    int i = blockIdx.x * 256 + threadIdx.x;
    if (i < total) {
        float v = A[i];
        __nv_bfloat16 h = __float2bfloat16(v);
        Ah[i] = h;
        Al[i] = __float2bfloat16(v - __bfloat162float(h));
    }
}

// W [K,N] row-major -> T [N,K] bf16 hi/lo
__global__ void transpose_split(const float* __restrict__ W,
                                __nv_bfloat16* __restrict__ Th,
                                __nv_bfloat16* __restrict__ Tl, int K, int N)
{
    __shared__ float t[32][33];
    const int k0 = blockIdx.y * 32, n0 = blockIdx.x * 32;
    const int tx = threadIdx.x, ty = threadIdx.y;  // 32 x 8
    for (int i = ty; i < 32; i += 8) {
        int k = k0 + i, n = n0 + tx;
        t[i][tx] = (n < N && k < K) ? W[(size_t)k * N + n] : 0.f;
    }
    __syncthreads();
    for (int i = ty; i < 32; i += 8) {
        int n = n0 + i, k = k0 + tx;
        if (n < N && k < K) {
            float v = t[tx][i];
            __nv_bfloat16 h = __float2bfloat16(v);
            Th[(size_t)n * K + k] = h;
            Tl[(size_t)n * K + k] = __float2bfloat16(v - __bfloat162float(h));
        }
    }
}

// ================= split-bf16 GEMM on mma.sync (HMMA) =================
// C[M,N] = A[M,K] @ B[K,N]; A as (Ah,Al)[M,K] bf16, B transposed (Bth,Btl)[N,K].
// CTA: 128x128 C tile, 8 warps (2m x 4n), each warp 64x32 via m16n8k16.
// BK=32, cp.async double buffer. SMEM matrix stride = 112B (conflict-free ldmatrix).
#define MAT_BYTES  (128 * 112)           // one 128x32 bf16 matrix (padded rows)
#define STAGE_BYTES (4 * MAT_BYTES)      // Ah, Al, Bh, Bl

__global__ void __launch_bounds__(256) mma_gemm(
    const __nv_bfloat16* __restrict__ Ah, const __nv_bfloat16* __restrict__ Al,
    const __nv_bfloat16* __restrict__ Bth, const __nv_bfloat16* __restrict__ Btl,
    float* __restrict__ C, int M, int N, int K)
{
    extern __shared__ char smem[];
    const uint32_t sb = smem_u32(smem);
    const int tid = threadIdx.x;
    const int lane = tid & 31, wid = tid >> 5;
    const int warp_m = wid & 1, warp_n = wid >> 1;
    const int row0 = blockIdx.y * 128, col0 = blockIdx.x * 128;
    const int nchunk = K >> 5;

    float acc[4][4][4];
#pragma unroll
    for (int a = 0; a < 4; a++)
#pragma unroll
        for (int b = 0; b < 4; b++)
#pragma unroll
            for (int c = 0; c < 4; c++) acc[a][b][c] = 0.f;

    // ldmatrix per-thread source offsets
    const int mt = lane >> 3, rin = lane & 7;
    const uint32_t a_off = (uint32_t)((warp_m * 64 + (mt & 1) * 8 + rin) * 112 + ((mt >> 1) * 8) * 2);
    const uint32_t b_off = (uint32_t)((warp_n * 32 + ((mt >= 2) ? 8 : 0) + rin) * 112 + ((mt & 1) * 8) * 2);

    auto load_chunk = [&](int c) {
        const int k0 = c * 32;
        const uint32_t st = sb + (uint32_t)(c & 1) * STAGE_BYTES;
#pragma unroll
        for (int i = 0; i < 8; i++) {
            int v = tid + i * 256;
            int mat = v >> 9, r = (v >> 2) & 127, c16 = v & 3;
            uint32_t dst = st + mat * MAT_BYTES + r * 112 + c16 * 16;
            const __nv_bfloat16* srcp;
            int sz = 16;
            if (mat == 0)      srcp = Ah + (size_t)(row0 + r) * K + k0 + c16 * 8;
            else if (mat == 1) srcp = Al + (size_t)(row0 + r) * K + k0 + c16 * 8;
            else {
                int n = col0 + r;
                int nn = (n < N) ? n : 0;
                if (n >= N) sz = 0;
                srcp = (mat == 2 ? Bth : Btl) + (size_t)nn * K + k0 + c16 * 8;
            }
            asm volatile("cp.async.cg.shared.global [%0], [%1], 16, %2;"
                         :: "r"(dst), "l"(srcp), "r"(sz));
        }
        asm volatile("cp.async.commit_group;" ::: "memory");
    };

    load_chunk(0);

    for (int c = 0; c < nchunk; c++) {
        if (c + 1 < nchunk) {
            load_chunk(c + 1);
            asm volatile("cp.async.wait_group 1;" ::: "memory");
        } else {
            asm volatile("cp.async.wait_group 0;" ::: "memory");
        }
        __syncthreads();

        const uint32_t st = sb + (uint32_t)(c & 1) * STAGE_BYTES;
#pragma unroll
        for (int ks = 0; ks < 2; ks++) {
            uint32_t ah[4][4], al[4][4];
#pragma unroll
            for (int mi = 0; mi < 4; mi++) {
                uint32_t addr = st + a_off + mi * (16 * 112) + ks * 32;
                asm volatile("ldmatrix.sync.aligned.m8n8.x4.shared.b16 {%0,%1,%2,%3}, [%4];"
                             : "=r"(ah[mi][0]), "=r"(ah[mi][1]), "=r"(ah[mi][2]), "=r"(ah[mi][3])
                             : "r"(addr));
                asm volatile("ldmatrix.sync.aligned.m8n8.x4.shared.b16 {%0,%1,%2,%3}, [%4];"
                             : "=r"(al[mi][0]), "=r"(al[mi][1]), "=r"(al[mi][2]), "=r"(al[mi][3])
                             : "r"(addr + MAT_BYTES));
            }
#pragma unroll
            for (int b2 = 0; b2 < 2; b2++) {
                uint32_t bh[4], bl[4];
                uint32_t baddr = st + 2 * MAT_BYTES + b_off + b2 * (16 * 112) + ks * 32;
                asm volatile("ldmatrix.sync.aligned.m8n8.x4.shared.b16 {%0,%1,%2,%3}, [%4];"
                             : "=r"(bh[0]), "=r"(bh[1]), "=r"(bh[2]), "=r"(bh[3]) : "r"(baddr));
                asm volatile("ldmatrix.sync.aligned.m8n8.x4.shared.b16 {%0,%1,%2,%3}, [%4];"
                             : "=r"(bl[0]), "=r"(bl[1]), "=r"(bl[2]), "=r"(bl[3])
                             : "r"(baddr + MAT_BYTES));
                // product-major order: consecutive mmas hit distinct accumulators
#pragma unroll
                for (int p = 0; p < 3; p++) {
#pragma unroll
                    for (int mi = 0; mi < 4; mi++) {
#pragma unroll
                        for (int hf = 0; hf < 2; hf++) {
                            const int nt = b2 * 2 + hf;
                            const uint32_t* A_ = (p == 2) ? al[mi] : ah[mi];
                            const uint32_t* B_ = (p == 1) ? bl : bh;
                            asm volatile(
                                "mma.sync.aligned.m16n8k16.row.col.f32.bf16.bf16.f32 "
                                "{%0,%1,%2,%3},{%4,%5,%6,%7},{%8,%9},{%0,%1,%2,%3};"
                                : "+f"(acc[mi][nt][0]), "+f"(acc[mi][nt][1]),
                                  "+f"(acc[mi][nt][2]), "+f"(acc[mi][nt][3])
                                : "r"(A_[0]), "r"(A_[1]), "r"(A_[2]), "r"(A_[3]),
                                  "r"(B_[hf * 2]), "r"(B_[hf * 2 + 1]));
                        }
                    }
                }
            }
        }
        __syncthreads();
    }

    // epilogue: c0,c1 = row g, cols 2c..; c2,c3 = row g+8
    const int g = lane >> 2, c2 = lane & 3;
#pragma unroll
    for (int mi = 0; mi < 4; mi++) {
        const int r = row0 + warp_m * 64 + mi * 16 + g;
#pragma unroll
        for (int nt = 0; nt < 4; nt++) {
            const int col = col0 + warp_n * 32 + nt * 8 + c2 * 2;
            if (col < N) {
                *(float2*)(C + (size_t)r * N + col)       = make_float2(acc[mi][nt][0], acc[mi][nt][1]);
                *(float2*)(C + (size_t)(r + 8) * N + col) = make_float2(acc[mi][nt][2], acc[mi][nt][3]);
            }
        }
    }
}

// ---------------- compressed tokens ----------------
__global__ void compress_kernel(const float* __restrict__ wck,
                                const float* __restrict__ wcv,
                                const float* __restrict__ pe)
{
    const int m = blockIdx.x, h = blockIdx.y, d = threadIdx.x;  // 64 threads
    float a = 0.f, b = 0.f;
    for (int t = 0; t < 64; t++) {
        const float wk = wck[h * 64 + t];
        const float wv = wcv[h * 64 + t];
        const int row = m * 64 + t;
        a = fmaf(g_kvg[row * 352 + h * 64 + d] + pe[(h * 64 + t) * 64 + d], wk, a);
        b = fmaf(g_kvg[row * 352 + 128 + h * 64 + d], wv, b);
    }
    g_ck[(m * 2 + h) * 64 + d] = a;
    g_cv[(m * 2 + h) * 64 + d] = b;
}

// ---------------- compressed attention + inline top-k block selection ----------------
__global__ void __launch_bounds__(128) comp_attn_kernel(int ntok)
{
    const int n = blockIdx.x, h = blockIdx.y;
    const int tid = threadIdx.x;
    const int M = ntok >> 6;
    __shared__ float sq[1024];
    __shared__ float sck[MMAX * 64];
    __shared__ float scv[MMAX * 64];
    __shared__ float lg[16 * 32];
    __shared__ float ssum[32];

    for (int i = tid; i < 1024; i += 128) sq[i] = g_q[n * 2048 + h * 1024 + i];
    for (int i = tid; i < M * 64; i += 128) {
        int m = i >> 6, d = i & 63;
        sck[i] = g_ck[(m * 2 + h) * 64 + d];
        scv[i] = g_cv[(m * 2 + h) * 64 + d];
    }
    __syncthreads();

    const int mvis = (n >= 63) ? (((n - 63) >> 6) + 1) : 0;

    for (int e = tid; e < 16 * M; e += 128) {
        int g = e / M, m = e - g * M;
        float a = 0.f;
#pragma unroll 16
        for (int d = 0; d < 64; d++) a = fmaf(sq[g * 64 + d], sck[m * 64 + d], a);
        lg[g * 32 + m] = a * 0.125f;
    }
    __syncthreads();

    if (tid < 16) {
        const int g = tid;
        if (mvis == 0) {
            for (int m = 0; m < M; m++) lg[g * 32 + m] = 0.f;
        } else {
            float mx = -INFINITY;
            for (int m = 0; m < mvis; m++) mx = fmaxf(mx, lg[g * 32 + m]);
            float s = 0.f;
            for (int m = 0; m < mvis; m++) {
                float p = __expf(lg[g * 32 + m] - mx);
                lg[g * 32 + m] = p; s += p;
            }
            const float inv = 1.f / s;
            for (int m = 0; m < mvis; m++) lg[g * 32 + m] *= inv;
            for (int m = mvis; m < M; m++) lg[g * 32 + m] = 0.f;
        }
    }
    __syncthreads();

    for (int e = tid; e < 1024; e += 128) {
        int g = e >> 6, d = e & 63;
        float a = 0.f;
        for (int m = 0; m < mvis; m++) a = fmaf(lg[g * 32 + m], scv[m * 64 + d], a);
        g_comp[n * 2048 + h * 1024 + e] = a;
    }

    if (tid < 32) {
        float s = 0.f;
        if (tid < M)
            for (int g = 0; g < 16; g++) s += lg[g * 32 + tid];
        ssum[tid] = s;
    }
    __syncthreads();

    if (tid == 0) {
        const int qblk = n >> 6;
        unsigned sel = 0;
        if (qblk + 1 <= 16) {
            sel = (1u << (qblk + 1)) - 1u;
        } else {
            float sc[32];
            for (int m = 0; m < 32; m++) {
                if (m > qblk)                                  sc[m] = -INFINITY;
                else if (m == 0 || m == qblk || m == qblk - 1) sc[m] = INFINITY;
                else                                           sc[m] = ssum[m];
            }
            for (int t = 0; t < 16; t++) {
                int best = 0; float bv = -INFINITY;
                for (int m = 0; m < 32; m++) {
                    if ((sel >> m) & 1u) continue;
                    if (sc[m] > bv) { bv = sc[m]; best = m; }
                }
                sel |= 1u << best;
            }
        }
        g_sel[n * 2 + h] = sel;
    }
}

// ---------------- main attention: sparse + window branches, fused gating ----------------
__global__ void __launch_bounds__(256) main_attn_kernel(int ntok)
{
    const int n = blockIdx.x, h = blockIdx.y;
    const int tid = threadIdx.x;
    __shared__ float sq[1024];
    __shared__ float sk[64 * 65];
    __shared__ float sv[64 * 64];
    __shared__ float lg[1024];
    __shared__ float pw[1024];
    __shared__ float hm[2][16], hl[2][16], hr[2][16];

    for (int i = tid; i < 1024; i += 256) sq[i] = g_q[n * 2048 + h * 1024 + i];
    if (tid < 32) { hm[tid >> 4][tid & 15] = -INFINITY; hl[tid >> 4][tid & 15] = 0.f; }
    float acc_s[4] = {0, 0, 0, 0}, acc_w[4] = {0, 0, 0, 0};

    const int qblk = n >> 6;
    const unsigned sel = g_sel[n * 2 + h];
    const int wlo = n - 512;
    __syncthreads();

    for (int c = 0; c <= qblk; c++) {
        const bool as = (sel >> c) & 1u;
        const bool aw = (c * 64 + 63) >= wlo;
        if (!as && !aw) continue;
        const int jn = min(63, n - c * 64);

        for (int i = tid; i < 4096; i += 256) {
            int j = i >> 6, d = i & 63;
            bool ok = (j <= jn);
            int gi = (c * 64 + j) * 352 + h * 64 + d;
            sk[j * 65 + d] = ok ? g_kvg[gi] : 0.f;
            sv[j * 64 + d] = ok ? g_kvg[gi + 128] : 0.f;
        }
        __syncthreads();

#pragma unroll
        for (int i = 0; i < 4; i++) {
            int e = tid + i * 256;
            int g = e >> 6, j = e & 63;
            float a = 0.f;
#pragma unroll 16
            for (int d = 0; d < 64; d++) a = fmaf(sq[g * 64 + d], sk[j * 65 + d], a);
            lg[e] = a * 0.125f;
        }
        __syncthreads();

        if (tid < 32) {
            const int br = tid >> 4, g = tid & 15;
            const bool act = br ? aw : as;
            float r = 1.f;
            if (act) {
                const int j0 = br ? max(0, wlo - c * 64) : 0;
                float cm = -INFINITY;
                for (int j = j0; j <= jn; j++) cm = fmaxf(cm, lg[g * 64 + j]);
                const float om = hm[br][g];
                const float nm = fmaxf(om, cm);
                r = __expf(om - nm);
                hm[br][g] = nm;
            }
            hr[br][g] = r;
        }
        __syncthreads();

        const int jw0 = max(0, wlo - c * 64);
#pragma unroll
        for (int i = 0; i < 4; i++) {
            int e = tid + i * 256;
            int g = e >> 6, j = e & 63;
            const float l = lg[e];
            const bool jc = (j <= jn);
            lg[e] = (as && jc)             ? __expf(l - hm[0][g]) : 0.f;
            pw[e] = (aw && jc && j >= jw0) ? __expf(l - hm[1][g]) : 0.f;
        }
        __syncthreads();

        if (tid < 32) {
            const int br = tid >> 4, g = tid & 15;
            const float* pp = br ? pw : lg;
            float s = 0.f;
            for (int j = 0; j < 64; j++) s += pp[g * 64 + j];
            hl[br][g] = hl[br][g] * hr[br][g] + s;
        }
#pragma unroll
        for (int i = 0; i < 4; i++) {
            int e = tid + i * 256;
            int g = e >> 6, d = e & 63;
            float a_s = acc_s[i] * hr[0][g];
            float a_w = acc_w[i] * hr[1][g];
#pragma unroll 16
            for (int j = 0; j < 64; j++) {
                const float vv = sv[j * 64 + d];
                a_s = fmaf(lg[g * 64 + j], vv, a_s);
                a_w = fmaf(pw[g * 64 + j], vv, a_w);
            }
            acc_s[i] = a_s; acc_w[i] = a_w;
        }
        __syncthreads();
    }

#pragma unroll
    for (int i = 0; i < 4; i++) {
        int e = tid + i * 256;
        int g = e >> 6;
        const int hq = h * 16 + g;
        const float gl0 = g_kvg[n * 352 + 256 + hq * 3 + 0];
        const float gl1 = g_kvg[n * 352 + 256 + hq * 3 + 1];
        const float gl2 = g_kvg[n * 352 + 256 + hq * 3 + 2];
        const float g0 = 1.f / (1.f + __expf(-gl0));
        const float g1 = 1.f / (1.f + __expf(-gl1));
        const float g2 = 1.f / (1.f + __expf(-gl2));
        const float comp = g_comp[n * 2048 + h * 1024 + e];
        g_fused[n * 2048 + h * 1024 + e] =
            g0 * comp + g1 * (acc_s[i] / hl[0][g]) + g2 * (acc_w[i] / hl[1][g]);
    }
}

// ---------------- launch ----------------
extern "C" void kernel_launch(void* const* d_in, const int* in_sizes, int n_in,
                              void* d_out, int out_size)
{
    const float* x   = (const float*)d_in[0];
    const float* Wq  = (const float*)d_in[2];
    const float* Wk  = (const float*)d_in[3];
    const float* Wv  = (const float*)d_in[4];
    const float* Wo  = (const float*)d_in[5];
    const float* Wg  = (const float*)d_in[6];
    const float* wck = (const float*)d_in[7];
    const float* wcv = (const float*)d_in[8];
    const float* pe  = (const float*)d_in[9];
    float* out = (float*)d_out;

    const int ntok = in_sizes[0] / 2048;     // T = 2048
    const int M = ntok / 64;

    float *q, *kvg, *fused;
    cudaGetSymbolAddress((void**)&q,     g_q);
    cudaGetSymbolAddress((void**)&kvg,   g_kvg);
    cudaGetSymbolAddress((void**)&fused, g_fused);

    __nv_bfloat16 *xh, *xl, *fh, *fl, *wqh, *wql, *woh, *wol, *wkvgh, *wkvgl;
    cudaGetSymbolAddress((void**)&xh, g_xh);     cudaGetSymbolAddress((void**)&xl, g_xl);
    cudaGetSymbolAddress((void**)&fh, g_fh);     cudaGetSymbolAddress((void**)&fl, g_fl);
    cudaGetSymbolAddress((void**)&wqh, g_wqt_h); cudaGetSymbolAddress((void**)&wql, g_wqt_l);
    cudaGetSymbolAddress((void**)&woh, g_wot_h); cudaGetSymbolAddress((void**)&wol, g_wot_l);
    cudaGetSymbolAddress((void**)&wkvgh, g_wkvgt_h);
    cudaGetSymbolAddress((void**)&wkvgl, g_wkvgt_l);

    const int SMEM_GEMM = 2 * STAGE_BYTES;   // 114688
    cudaFuncSetAttribute(mma_gemm, cudaFuncAttributeMaxDynamicSharedMemorySize, SMEM_GEMM);

    const int tot = ntok * 2048;
    dim3 tb(32, 8);

    // prep: split activations, transpose+split weights
    split_fp32<<<(tot + 255) / 256, 256>>>(x, xh, xl, tot);
    transpose_split<<<dim3(64, 64), tb>>>(Wq, wqh, wql, 2048, 2048);
    transpose_split<<<dim3(4,  64), tb>>>(Wk, wkvgh,              wkvgl,              2048, 128);
    transpose_split<<<dim3(4,  64), tb>>>(Wv, wkvgh + 128 * 2048, wkvgl + 128 * 2048, 2048, 128);
    transpose_split<<<dim3(3,  64), tb>>>(Wg, wkvgh + 256 * 2048, wkvgl + 256 * 2048, 2048, 96);
    transpose_split<<<dim3(64, 64), tb>>>(Wo, woh, wol, 2048, 2048);

    // projections on tensor cores (HMMA)
    mma_gemm<<<dim3(16, ntok / 128), 256, SMEM_GEMM>>>(xh, xl, wqh, wql, q, ntok, 2048, 2048);
    mma_gemm<<<dim3(3,  ntok / 128), 256, SMEM_GEMM>>>(xh, xl, wkvgh, wkvgl, kvg, ntok, 352, 2048);

    compress_kernel<<<dim3(M, 2), 64>>>(wck, wcv, pe);
    comp_attn_kernel<<<dim3(ntok, 2), 128>>>(ntok);
    main_attn_kernel<<<dim3(ntok, 2), 256>>>(ntok);

    // output projection
    split_fp32<<<(tot + 255) / 256, 256>>>(fused, fh, fl, tot);
    mma_gemm<<<dim3(16, ntok / 128), 256, SMEM_GEMM>>>(fh, fl, woh, wol, out, ntok, 2048, 2048);
}

// round 4
// speedup vs baseline: 1.7982x; 1.2155x over previous
#include <cuda_runtime.h>
#include <cuda_bf16.h>
#include <math.h>
#include <stdint.h>

// Problem constants (T=2048, H=2048, HQ=32, HKV=2, D=64, G=16, M<=32)
#define TMAX 2048
#define MMAX 32

// ---------------- scratch (no allocation allowed) ----------------
__device__ float    g_q[TMAX * 2048];      // [n, HQ*D]
__device__ float    g_kvg[TMAX * 352];     // [n, k(128) | v(128) | gate(96)]
__device__ float    g_ck[MMAX * 2 * 64];
__device__ float    g_cv[MMAX * 2 * 64];
__device__ float    g_comp[TMAX * 2048];
__device__ float    g_fused[TMAX * 2048];
__device__ unsigned g_sel[TMAX * 2];

// bf16 split operands for tensor-core GEMMs
__device__ __nv_bfloat16 g_xh[2048 * 2048], g_xl[2048 * 2048];
__device__ __nv_bfloat16 g_fh[2048 * 2048], g_fl[2048 * 2048];
__device__ __nv_bfloat16 g_wqt_h[2048 * 2048], g_wqt_l[2048 * 2048];   // Wq^T [N,K]
__device__ __nv_bfloat16 g_wot_h[2048 * 2048], g_wot_l[2048 * 2048];   // Wo^T
__device__ __nv_bfloat16 g_wkvgt_h[352 * 2048], g_wkvgt_l[352 * 2048]; // [Wk|Wv|Wg]^T

__device__ __forceinline__ uint32_t smem_u32(const void* p) {
    uint32_t a;
    asm("{ .reg .u64 t; cvta.to.shared.u64 t, %1; cvt.u32.u64 %0, t; }" : "=r"(a) : "l"(p));
    return a;
}

// ---------------- packed f32x2 helpers (FFMA2, sm_100+) ----------------
__device__ __forceinline__ unsigned long long pk2(float x, float y) {
    unsigned long long r;
    asm("mov.b64 %0, {%1,%2};" : "=l"(r) : "f"(x), "f"(y));
    return r;
}
__device__ __forceinline__ unsigned long long pk2f2(float2 v) { return pk2(v.x, v.y); }
__device__ __forceinline__ void upk2(unsigned long long r, float& x, float& y) {
    asm("mov.b64 {%0,%1}, %2;" : "=f"(x), "=f"(y) : "l"(r));
}
__device__ __forceinline__ unsigned long long fma2(unsigned long long a,
                                                   unsigned long long b,
                                                   unsigned long long c) {
    unsigned long long d;
    asm("fma.rn.f32x2 %0, %1, %2, %3;" : "=l"(d) : "l"(a), "l"(b), "l"(c));
    return d;
}
__device__ __forceinline__ unsigned long long mul2(unsigned long long a,
                                                   unsigned long long b) {
    unsigned long long d;
    asm("mul.rn.f32x2 %0, %1, %2;" : "=l"(d) : "l"(a), "l"(b));
    return d;
}

// ================= prep kernels =================
__global__ void split_fp32(const float* __restrict__ A,
                           __nv_bfloat16* __restrict__ Ah,
                           __nv_bfloat16* __restrict__ Al, int total)
{
    int i = blockIdx.x * 256 + threadIdx.x;
    if (i < total) {
        float v = A[i];
        __nv_bfloat16 h = __float2bfloat16(v);
        Ah[i] = h;
        Al[i] = __float2bfloat16(v - __bfloat162float(h));
    }
}

// W [K,N] row-major -> T [N,K] bf16 hi/lo
__global__ void transpose_split(const float* __restrict__ W,
                                __nv_bfloat16* __restrict__ Th,
                                __nv_bfloat16* __restrict__ Tl, int K, int N)
{
    __shared__ float t[32][33];
    const int k0 = blockIdx.y * 32, n0 = blockIdx.x * 32;
    const int tx = threadIdx.x, ty = threadIdx.y;  // 32 x 8
    for (int i = ty; i < 32; i += 8) {
        int k = k0 + i, n = n0 + tx;
        t[i][tx] = (n < N && k < K) ? W[(size_t)k * N + n] : 0.f;
    }
    __syncthreads();
    for (int i = ty; i < 32; i += 8) {
        int n = n0 + i, k = k0 + tx;
        if (n < N && k < K) {
            float v = t[tx][i];
            __nv_bfloat16 h = __float2bfloat16(v);
            Th[(size_t)n * K + k] = h;
            Tl[(size_t)n * K + k] = __float2bfloat16(v - __bfloat162float(h));
        }
    }
}

// ================= split-bf16 GEMM on mma.sync (HMMA) =================
#define MAT_BYTES  (128 * 112)
#define STAGE_BYTES (4 * MAT_BYTES)

__global__ void __launch_bounds__(256) mma_gemm(
    const __nv_bfloat16* __restrict__ Ah, const __nv_bfloat16* __restrict__ Al,
    const __nv_bfloat16* __restrict__ Bth, const __nv_bfloat16* __restrict__ Btl,
    float* __restrict__ C, int M, int N, int K)
{
    extern __shared__ char smem[];
    const uint32_t sb = smem_u32(smem);
    const int tid = threadIdx.x;
    const int lane = tid & 31, wid = tid >> 5;
    const int warp_m = wid & 1, warp_n = wid >> 1;
    const int row0 = blockIdx.y * 128, col0 = blockIdx.x * 128;
    const int nchunk = K >> 5;

    float acc[4][4][4];
#pragma unroll
    for (int a = 0; a < 4; a++)
#pragma unroll
        for (int b = 0; b < 4; b++)
#pragma unroll
            for (int c = 0; c < 4; c++) acc[a][b][c] = 0.f;

    const int mt = lane >> 3, rin = lane & 7;
    const uint32_t a_off = (uint32_t)((warp_m * 64 + (mt & 1) * 8 + rin) * 112 + ((mt >> 1) * 8) * 2);
    const uint32_t b_off = (uint32_t)((warp_n * 32 + ((mt >= 2) ? 8 : 0) + rin) * 112 + ((mt & 1) * 8) * 2);

    auto load_chunk = [&](int c) {
        const int k0 = c * 32;
        const uint32_t st = sb + (uint32_t)(c & 1) * STAGE_BYTES;
#pragma unroll
        for (int i = 0; i < 8; i++) {
            int v = tid + i * 256;
            int mat = v >> 9, r = (v >> 2) & 127, c16 = v & 3;
            uint32_t dst = st + mat * MAT_BYTES + r * 112 + c16 * 16;
            const __nv_bfloat16* srcp;
            int sz = 16;
            if (mat == 0)      srcp = Ah + (size_t)(row0 + r) * K + k0 + c16 * 8;
            else if (mat == 1) srcp = Al + (size_t)(row0 + r) * K + k0 + c16 * 8;
            else {
                int n = col0 + r;
                int nn = (n < N) ? n : 0;
                if (n >= N) sz = 0;
                srcp = (mat == 2 ? Bth : Btl) + (size_t)nn * K + k0 + c16 * 8;
            }
            asm volatile("cp.async.cg.shared.global [%0], [%1], 16, %2;"
                         :: "r"(dst), "l"(srcp), "r"(sz));
        }
        asm volatile("cp.async.commit_group;" ::: "memory");
    };

    load_chunk(0);

    for (int c = 0; c < nchunk; c++) {
        if (c + 1 < nchunk) {
            load_chunk(c + 1);
            asm volatile("cp.async.wait_group 1;" ::: "memory");
        } else {
            asm volatile("cp.async.wait_group 0;" ::: "memory");
        }
        __syncthreads();

        const uint32_t st = sb + (uint32_t)(c & 1) * STAGE_BYTES;
#pragma unroll
        for (int ks = 0; ks < 2; ks++) {
            uint32_t ah[4][4], al[4][4];
#pragma unroll
            for (int mi = 0; mi < 4; mi++) {
                uint32_t addr = st + a_off + mi * (16 * 112) + ks * 32;
                asm volatile("ldmatrix.sync.aligned.m8n8.x4.shared.b16 {%0,%1,%2,%3}, [%4];"
                             : "=r"(ah[mi][0]), "=r"(ah[mi][1]), "=r"(ah[mi][2]), "=r"(ah[mi][3])
                             : "r"(addr));
                asm volatile("ldmatrix.sync.aligned.m8n8.x4.shared.b16 {%0,%1,%2,%3}, [%4];"
                             : "=r"(al[mi][0]), "=r"(al[mi][1]), "=r"(al[mi][2]), "=r"(al[mi][3])
                             : "r"(addr + MAT_BYTES));
            }
#pragma unroll
            for (int b2 = 0; b2 < 2; b2++) {
                uint32_t bh[4], bl[4];
                uint32_t baddr = st + 2 * MAT_BYTES + b_off + b2 * (16 * 112) + ks * 32;
                asm volatile("ldmatrix.sync.aligned.m8n8.x4.shared.b16 {%0,%1,%2,%3}, [%4];"
                             : "=r"(bh[0]), "=r"(bh[1]), "=r"(bh[2]), "=r"(bh[3]) : "r"(baddr));
                asm volatile("ldmatrix.sync.aligned.m8n8.x4.shared.b16 {%0,%1,%2,%3}, [%4];"
                             : "=r"(bl[0]), "=r"(bl[1]), "=r"(bl[2]), "=r"(bl[3])
                             : "r"(baddr + MAT_BYTES));
#pragma unroll
                for (int p = 0; p < 3; p++) {
#pragma unroll
                    for (int mi = 0; mi < 4; mi++) {
#pragma unroll
                        for (int hf = 0; hf < 2; hf++) {
                            const int nt = b2 * 2 + hf;
                            const uint32_t* A_ = (p == 2) ? al[mi] : ah[mi];
                            const uint32_t* B_ = (p == 1) ? bl : bh;
                            asm volatile(
                                "mma.sync.aligned.m16n8k16.row.col.f32.bf16.bf16.f32 "
                                "{%0,%1,%2,%3},{%4,%5,%6,%7},{%8,%9},{%0,%1,%2,%3};"
                                : "+f"(acc[mi][nt][0]), "+f"(acc[mi][nt][1]),
                                  "+f"(acc[mi][nt][2]), "+f"(acc[mi][nt][3])
                                : "r"(A_[0]), "r"(A_[1]), "r"(A_[2]), "r"(A_[3]),
                                  "r"(B_[hf * 2]), "r"(B_[hf * 2 + 1]));
                        }
                    }
                }
            }
        }
        __syncthreads();
    }

    const int g = lane >> 2, c2 = lane & 3;
#pragma unroll
    for (int mi = 0; mi < 4; mi++) {
        const int r = row0 + warp_m * 64 + mi * 16 + g;
#pragma unroll
        for (int nt = 0; nt < 4; nt++) {
            const int col = col0 + warp_n * 32 + nt * 8 + c2 * 2;
            if (col < N) {
                *(float2*)(C + (size_t)r * N + col)       = make_float2(acc[mi][nt][0], acc[mi][nt][1]);
                *(float2*)(C + (size_t)(r + 8) * N + col) = make_float2(acc[mi][nt][2], acc[mi][nt][3]);
            }
        }
    }
}

// ---------------- compressed tokens ----------------
__global__ void compress_kernel(const float* __restrict__ wck,
                                const float* __restrict__ wcv,
                                const float* __restrict__ pe)
{
    const int m = blockIdx.x, h = blockIdx.y, d = threadIdx.x;  // 64 threads
    float a = 0.f, b = 0.f;
    for (int t = 0; t < 64; t++) {
        const float wk = wck[h * 64 + t];
        const float wv = wcv[h * 64 + t];
        const int row = m * 64 + t;
        a = fmaf(g_kvg[row * 352 + h * 64 + d] + pe[(h * 64 + t) * 64 + d], wk, a);
        b = fmaf(g_kvg[row * 352 + 128 + h * 64 + d], wv, b);
    }
    g_ck[(m * 2 + h) * 64 + d] = a;
    g_cv[(m * 2 + h) * 64 + d] = b;
}

// ---------------- compressed attention + inline top-k block selection ----------------
// 128 threads; f32x2 packed QK (d-pairs) and PV (d-pairs).
__global__ void __launch_bounds__(128) comp_attn_kernel(int ntok)
{
    const int n = blockIdx.x, h = blockIdx.y;
    const int tid = threadIdx.x;
    const int M = ntok >> 6;
    __shared__ float  sq[1024];
    __shared__ float2 ckp[32 * 33];           // [d2][m] pairs, padded
    __shared__ float  scv[MMAX * 64];
    __shared__ float  lg[16 * 32];
    __shared__ float  ssum[32];

    for (int i = tid; i < 1024; i += 128) sq[i] = g_q[n * 2048 + h * 1024 + i];
    for (int i = tid; i < M * 32; i += 128) {         // ck pairs
        int m = i >> 5, d2 = i & 31;
        ckp[d2 * 33 + m] = *(const float2*)&g_ck[(m * 2 + h) * 64 + 2 * d2];
    }
    for (int i = tid; i < M * 64; i += 128) {
        int m = i >> 6, d = i & 63;
        scv[i] = g_cv[(m * 2 + h) * 64 + d];
    }
    __syncthreads();

    const int mvis = (n >= 63) ? (((n - 63) >> 6) + 1) : 0;

    // QK: 512 logits, 4 per thread, packed over d
#pragma unroll
    for (int i = 0; i < 4; i++) {
        int e = tid + i * 128;
        int g = e >> 5, m = e & 31;
        unsigned long long acc = 0ull;
#pragma unroll
        for (int d2 = 0; d2 < 32; d2++) {
            unsigned long long qp = pk2f2(*(const float2*)&sq[g * 64 + 2 * d2]);
            unsigned long long kp = pk2f2(ckp[d2 * 33 + m]);
            acc = fma2(qp, kp, acc);
        }
        float x, y; upk2(acc, x, y);
        lg[g * 32 + m] = (x + y) * 0.125f;
    }
    __syncthreads();

    if (tid < 16) {
        const int g = tid;
        if (mvis == 0) {
            for (int m = 0; m < M; m++) lg[g * 32 + m] = 0.f;
        } else {
            float mx = -INFINITY;
            for (int m = 0; m < mvis; m++) mx = fmaxf(mx, lg[g * 32 + m]);
            float s = 0.f;
            for (int m = 0; m < mvis; m++) {
                float p = __expf(lg[g * 32 + m] - mx);
                lg[g * 32 + m] = p; s += p;
            }
            const float inv = 1.f / s;
            for (int m = 0; m < mvis; m++) lg[g * 32 + m] *= inv;
            for (int m = mvis; m < M; m++) lg[g * 32 + m] = 0.f;
        }
    }
    __syncthreads();

    // PV: 512 d-pairs, 4 per thread
#pragma unroll
    for (int i = 0; i < 4; i++) {
        int e2 = tid + i * 128;
        int g = e2 >> 5, d2 = e2 & 31;
        unsigned long long acc = 0ull;
        for (int m = 0; m < mvis; m++) {
            float p = lg[g * 32 + m];
            unsigned long long cv2 = pk2f2(*(const float2*)&scv[m * 64 + 2 * d2]);
            acc = fma2(pk2(p, p), cv2, acc);
        }
        float x, y; upk2(acc, x, y);
        *(float2*)&g_comp[n * 2048 + h * 1024 + g * 64 + 2 * d2] = make_float2(x, y);
    }

    if (tid < 32) {
        float s = 0.f;
        if (tid < M)
            for (int g = 0; g < 16; g++) s += lg[g * 32 + tid];
        ssum[tid] = s;
    }
    __syncthreads();

    if (tid == 0) {
        const int qblk = n >> 6;
        unsigned sel = 0;
        if (qblk + 1 <= 16) {
            sel = (1u << (qblk + 1)) - 1u;
        } else {
            float sc[32];
            for (int m = 0; m < 32; m++) {
                if (m > qblk)                                  sc[m] = -INFINITY;
                else if (m == 0 || m == qblk || m == qblk - 1) sc[m] = INFINITY;
                else                                           sc[m] = ssum[m];
            }
            for (int t = 0; t < 16; t++) {
                int best = 0; float bv = -INFINITY;
                for (int m = 0; m < 32; m++) {
                    if ((sel >> m) & 1u) continue;
                    if (sc[m] > bv) { bv = sc[m]; best = m; }
                }
                sel |= 1u << best;
            }
        }
        g_sel[n * 2 + h] = sel;
    }
}

// ---------------- main attention: sparse + window, f32x2 packed ----------------
// 256 threads, dynamic smem. QK packs over d; PV packs over (sparse,window) branch.
#define ATTN_SMEM 50304
__global__ void __launch_bounds__(256) main_attn_kernel(int ntok)
{
    extern __shared__ char dsm[];
    float*  sq  = (float*)dsm;                    // [16][64]
    float*  lg  = (float*)(dsm + 4096);           // [16][64] raw logits
    float2* pp  = (float2*)(dsm + 8192);          // [16][64] {p_s, p_w}
    float2* skp = (float2*)(dsm + 16384);         // [32][65] K d-pairs
    float*  sv  = (float*)(dsm + 33024);          // [64][64]
    float*  pm  = (float*)(dsm + 49408);          // [128] partials
    float*  hmm = (float*)(dsm + 49920);          // [2][16]
    float*  hll = hmm + 32;
    float*  hrr = hll + 32;

    const int n = blockIdx.x, h = blockIdx.y;
    const int tid = threadIdx.x;

    for (int i = tid; i < 1024; i += 256) sq[i] = g_q[n * 2048 + h * 1024 + i];
    if (tid < 32) { hmm[tid] = -INFINITY; hll[tid] = 0.f; }

    unsigned long long acc2[4] = {0ull, 0ull, 0ull, 0ull};
    const int gb = tid >> 6, d = tid & 63;

    const int qblk = n >> 6;
    const unsigned sel = g_sel[n * 2 + h];
    const int wlo = n - 512;
    __syncthreads();

    for (int c = 0; c <= qblk; c++) {
        const bool as = (sel >> c) & 1u;
        const bool aw = (c * 64 + 63) >= wlo;
        if (!as && !aw) continue;
        const int jn = min(63, n - c * 64);
        const int jw0 = max(0, wlo - c * 64);

        // load K (d-pair layout) and V
        for (int i = tid; i < 2048; i += 256) {
            int j = i >> 5, d2 = i & 31;
            skp[d2 * 65 + j] = (j <= jn)
                ? *(const float2*)&g_kvg[(c * 64 + j) * 352 + h * 64 + 2 * d2]
                : make_float2(0.f, 0.f);
        }
        for (int i = tid; i < 4096; i += 256) {
            int j = i >> 6;
            sv[i] = (j <= jn) ? g_kvg[(c * 64 + j) * 352 + h * 64 + 128 + (i & 63)] : 0.f;
        }
        __syncthreads();

        // QK (packed over d)
#pragma unroll
        for (int i = 0; i < 4; i++) {
            int e = tid + i * 256;
            int g = e >> 6, j = e & 63;
            unsigned long long a = 0ull;
#pragma unroll
            for (int d2 = 0; d2 < 32; d2++) {
                unsigned long long qp = pk2f2(*(const float2*)&sq[g * 64 + 2 * d2]);
                a = fma2(qp, pk2f2(skp[d2 * 65 + j]), a);
            }
            float x, y; upk2(a, x, y);
            lg[e] = (x + y) * 0.125f;
        }
        __syncthreads();

        // segmented max
        if (tid < 128) {
            const int br = tid >> 6, g = (tid >> 2) & 15, seg = tid & 3;
            const bool act = br ? aw : as;
            float m = -INFINITY;
            if (act) {
                const int lo = br ? max(seg * 16, jw0) : seg * 16;
                const int hi = min(seg * 16 + 15, jn);
                for (int j = lo; j <= hi; j++) m = fmaxf(m, lg[g * 64 + j]);
            }
            pm[tid] = m;
        }
        __syncthreads();
        if (tid < 32) {
            const int br = tid >> 4, g = tid & 15;
            const bool act = br ? aw : as;
            float r = 1.f;
            if (act) {
                const float* p = pm + br * 64 + g * 4;
                float cm = fmaxf(fmaxf(p[0], p[1]), fmaxf(p[2], p[3]));
                const float om = hmm[br * 16 + g];
                const float nm = fmaxf(om, cm);
                r = __expf(om - nm);
                hmm[br * 16 + g] = nm;
            }
            hrr[br * 16 + g] = r;
        }
        __syncthreads();

        // exp -> pp (branch-interleaved)
#pragma unroll
        for (int i = 0; i < 4; i++) {
            int e = tid + i * 256;
            int g = e >> 6, j = e & 63;
            const float l = lg[e];
            const bool jc = (j <= jn);
            float es = (as && jc)             ? __expf(l - hmm[g])      : 0.f;
            float ew = (aw && jc && j >= jw0) ? __expf(l - hmm[16 + g]) : 0.f;
            pp[g * 64 + j] = make_float2(es, ew);
        }
        __syncthreads();

        // segmented sum
        if (tid < 128) {
            const int br = tid >> 6, g = (tid >> 2) & 15, seg = tid & 3;
            float s = 0.f;
            for (int j = seg * 16; j < seg * 16 + 16; j++) {
                float2 v = pp[g * 64 + j];
                s += br ? v.y : v.x;
            }
            pm[tid] = s;
        }
        __syncthreads();
        if (tid < 32) {
            const int br = tid >> 4, g = tid & 15;
            const float* p = pm + br * 64 + g * 4;
            hll[br * 16 + g] = hll[br * 16 + g] * hrr[br * 16 + g]
                             + (p[0] + p[1]) + (p[2] + p[3]);
        }

        // PV (branch-packed): thread owns fixed d, g in {gb, gb+4, gb+8, gb+12}
#pragma unroll
        for (int i = 0; i < 4; i++) {
            const int g = gb + 4 * i;
            acc2[i] = mul2(acc2[i], pk2(hrr[g], hrr[16 + g]));
        }
        for (int j = 0; j <= jn; j++) {
            const float vv = sv[j * 64 + d];
            const unsigned long long v2 = pk2(vv, vv);
#pragma unroll
            for (int i = 0; i < 4; i++) {
                const int g = gb + 4 * i;
                acc2[i] = fma2(pk2f2(pp[g * 64 + j]), v2, acc2[i]);
            }
        }
        __syncthreads();
    }

    // gated fusion
#pragma unroll
    for (int i = 0; i < 4; i++) {
        const int g = gb + 4 * i;
        const int hq = h * 16 + g;
        const float gl0 = g_kvg[n * 352 + 256 + hq * 3 + 0];
        const float gl1 = g_kvg[n * 352 + 256 + hq * 3 + 1];
        const float gl2 = g_kvg[n * 352 + 256 + hq * 3 + 2];
        const float g0 = 1.f / (1.f + __expf(-gl0));
        const float g1 = 1.f / (1.f + __expf(-gl1));
        const float g2 = 1.f / (1.f + __expf(-gl2));
        float ax, ay; upk2(acc2[i], ax, ay);
        const float comp = g_comp[n * 2048 + h * 1024 + g * 64 + d];
        g_fused[n * 2048 + h * 1024 + g * 64 + d] =
            g0 * comp + g1 * (ax / hll[g]) + g2 * (ay / hll[16 + g]);
    }
}

// ---------------- launch ----------------
extern "C" void kernel_launch(void* const* d_in, const int* in_sizes, int n_in,
                              void* d_out, int out_size)
{
    const float* x   = (const float*)d_in[0];
    const float* Wq  = (const float*)d_in[2];
    const float* Wk  = (const float*)d_in[3];
    const float* Wv  = (const float*)d_in[4];
    const float* Wo  = (const float*)d_in[5];
    const float* Wg  = (const float*)d_in[6];
    const float* wck = (const float*)d_in[7];
    const float* wcv = (const float*)d_in[8];
    const float* pe  = (const float*)d_in[9];
    float* out = (float*)d_out;

    const int ntok = in_sizes[0] / 2048;     // T = 2048
    const int M = ntok / 64;

    float *q, *kvg, *fused;
    cudaGetSymbolAddress((void**)&q,     g_q);
    cudaGetSymbolAddress((void**)&kvg,   g_kvg);
    cudaGetSymbolAddress((void**)&fused, g_fused);

    __nv_bfloat16 *xh, *xl, *fh, *fl, *wqh, *wql, *woh, *wol, *wkvgh, *wkvgl;
    cudaGetSymbolAddress((void**)&xh, g_xh);     cudaGetSymbolAddress((void**)&xl, g_xl);
    cudaGetSymbolAddress((void**)&fh, g_fh);     cudaGetSymbolAddress((void**)&fl, g_fl);
    cudaGetSymbolAddress((void**)&wqh, g_wqt_h); cudaGetSymbolAddress((void**)&wql, g_wqt_l);
    cudaGetSymbolAddress((void**)&woh, g_wot_h); cudaGetSymbolAddress((void**)&wol, g_wot_l);
    cudaGetSymbolAddress((void**)&wkvgh, g_wkvgt_h);
    cudaGetSymbolAddress((void**)&wkvgl, g_wkvgt_l);

    const int SMEM_GEMM = 2 * STAGE_BYTES;   // 114688
    cudaFuncSetAttribute(mma_gemm, cudaFuncAttributeMaxDynamicSharedMemorySize, SMEM_GEMM);
    cudaFuncSetAttribute(main_attn_kernel, cudaFuncAttributeMaxDynamicSharedMemorySize, ATTN_SMEM);

    const int tot = ntok * 2048;
    dim3 tb(32, 8);

    split_fp32<<<(tot + 255) / 256, 256>>>(x, xh, xl, tot);
    transpose_split<<<dim3(64, 64), tb>>>(Wq, wqh, wql, 2048, 2048);
    transpose_split<<<dim3(4,  64), tb>>>(Wk, wkvgh,              wkvgl,              2048, 128);
    transpose_split<<<dim3(4,  64), tb>>>(Wv, wkvgh + 128 * 2048, wkvgl + 128 * 2048, 2048, 128);
    transpose_split<<<dim3(3,  64), tb>>>(Wg, wkvgh + 256 * 2048, wkvgl + 256 * 2048, 2048, 96);
    transpose_split<<<dim3(64, 64), tb>>>(Wo, woh, wol, 2048, 2048);

    mma_gemm<<<dim3(16, ntok / 128), 256, SMEM_GEMM>>>(xh, xl, wqh, wql, q, ntok, 2048, 2048);
    mma_gemm<<<dim3(3,  ntok / 128), 256, SMEM_GEMM>>>(xh, xl, wkvgh, wkvgl, kvg, ntok, 352, 2048);

    compress_kernel<<<dim3(M, 2), 64>>>(wck, wcv, pe);
    comp_attn_kernel<<<dim3(ntok, 2), 128>>>(ntok);
    main_attn_kernel<<<dim3(ntok, 2), 256, ATTN_SMEM>>>(ntok);

    split_fp32<<<(tot + 255) / 256, 256>>>(fused, fh, fl, tot);
    mma_gemm<<<dim3(16, ntok / 128), 256, SMEM_GEMM>>>(fh, fl, woh, wol, out, ntok, 2048, 2048);
}

// round 5
// speedup vs baseline: 1.8835x; 1.0474x over previous
#include <cuda_runtime.h>
#include <cuda_bf16.h>
#include <math.h>
#include <stdint.h>

// Problem constants (T=2048, H=2048, HQ=32, HKV=2, D=64, G=16, M<=32)
#define TMAX 2048
#define MMAX 32

// ---------------- scratch (no allocation allowed) ----------------
__device__ float    g_q[TMAX * 2048];      // [n, HQ*D]
__device__ float    g_kvg[TMAX * 352];     // [n, k(128) | v(128) | gate(96)]
__device__ float    g_ck[MMAX * 2 * 64];
__device__ float    g_cv[MMAX * 2 * 64];
__device__ float    g_comp[TMAX * 2048];
__device__ unsigned g_sel[TMAX * 2];

// bf16 split operands for tensor-core GEMMs
__device__ __nv_bfloat16 g_xh[2048 * 2048], g_xl[2048 * 2048];
__device__ __nv_bfloat16 g_fh[2048 * 2048], g_fl[2048 * 2048];
__device__ __nv_bfloat16 g_wqt_h[2048 * 2048], g_wqt_l[2048 * 2048];   // Wq^T [N,K]
__device__ __nv_bfloat16 g_wot_h[2048 * 2048], g_wot_l[2048 * 2048];   // Wo^T
__device__ __nv_bfloat16 g_wkvgt_h[352 * 2048], g_wkvgt_l[352 * 2048]; // [Wk|Wv|Wg]^T

__device__ __forceinline__ uint32_t smem_u32(const void* p) {
    uint32_t a;
    asm("{ .reg .u64 t; cvta.to.shared.u64 t, %1; cvt.u32.u64 %0, t; }" : "=r"(a) : "l"(p));
    return a;
}

// ---------------- packed f32x2 helpers (FFMA2, sm_100+) ----------------
__device__ __forceinline__ unsigned long long pk2(float x, float y) {
    unsigned long long r;
    asm("mov.b64 %0, {%1,%2};" : "=l"(r) : "f"(x), "f"(y));
    return r;
}
__device__ __forceinline__ unsigned long long pk2f2(float2 v) { return pk2(v.x, v.y); }
__device__ __forceinline__ void upk2(unsigned long long r, float& x, float& y) {
    asm("mov.b64 {%0,%1}, %2;" : "=f"(x), "=f"(y) : "l"(r));
}
__device__ __forceinline__ unsigned long long fma2(unsigned long long a,
                                                   unsigned long long b,
                                                   unsigned long long c) {
    unsigned long long d;
    asm("fma.rn.f32x2 %0, %1, %2, %3;" : "=l"(d) : "l"(a), "l"(b), "l"(c));
    return d;
}
__device__ __forceinline__ unsigned long long mul2(unsigned long long a,
                                                   unsigned long long b) {
    unsigned long long d;
    asm("mul.rn.f32x2 %0, %1, %2;" : "=l"(d) : "l"(a), "l"(b));
    return d;
}

// ================= prep kernels =================
__global__ void split_fp32(const float* __restrict__ A,
                           __nv_bfloat16* __restrict__ Ah,
                           __nv_bfloat16* __restrict__ Al, int total)
{
    int i = blockIdx.x * 256 + threadIdx.x;
    if (i < total) {
        float v = A[i];
        __nv_bfloat16 h = __float2bfloat16(v);
        Ah[i] = h;
        Al[i] = __float2bfloat16(v - __bfloat162float(h));
    }
}

// W [K,N] row-major -> T [N,K] bf16 hi/lo
__global__ void transpose_split(const float* __restrict__ W,
                                __nv_bfloat16* __restrict__ Th,
                                __nv_bfloat16* __restrict__ Tl, int K, int N)
{
    __shared__ float t[32][33];
    const int k0 = blockIdx.y * 32, n0 = blockIdx.x * 32;
    const int tx = threadIdx.x, ty = threadIdx.y;  // 32 x 8
    for (int i = ty; i < 32; i += 8) {
        int k = k0 + i, n = n0 + tx;
        t[i][tx] = (n < N && k < K) ? W[(size_t)k * N + n] : 0.f;
    }
    __syncthreads();
    for (int i = ty; i < 32; i += 8) {
        int n = n0 + i, k = k0 + tx;
        if (n < N && k < K) {
            float v = t[tx][i];
            __nv_bfloat16 h = __float2bfloat16(v);
            Th[(size_t)n * K + k] = h;
            Tl[(size_t)n * K + k] = __float2bfloat16(v - __bfloat162float(h));
        }
    }
}

// ================= split-bf16 GEMM on mma.sync (HMMA) =================
#define MAT_BYTES  (128 * 112)
#define STAGE_BYTES (4 * MAT_BYTES)

__global__ void __launch_bounds__(256) mma_gemm(
    const __nv_bfloat16* __restrict__ Ah, const __nv_bfloat16* __restrict__ Al,
    const __nv_bfloat16* __restrict__ Bth, const __nv_bfloat16* __restrict__ Btl,
    float* __restrict__ C, int M, int N, int K)
{
    extern __shared__ char smem[];
    const uint32_t sb = smem_u32(smem);
    const int tid = threadIdx.x;
    const int lane = tid & 31, wid = tid >> 5;
    const int warp_m = wid & 1, warp_n = wid >> 1;
    const int row0 = blockIdx.y * 128, col0 = blockIdx.x * 128;
    const int nchunk = K >> 5;

    float acc[4][4][4];
#pragma unroll
    for (int a = 0; a < 4; a++)
#pragma unroll
        for (int b = 0; b < 4; b++)
#pragma unroll
            for (int c = 0; c < 4; c++) acc[a][b][c] = 0.f;

    const int mt = lane >> 3, rin = lane & 7;
    const uint32_t a_off = (uint32_t)((warp_m * 64 + (mt & 1) * 8 + rin) * 112 + ((mt >> 1) * 8) * 2);
    const uint32_t b_off = (uint32_t)((warp_n * 32 + ((mt >= 2) ? 8 : 0) + rin) * 112 + ((mt & 1) * 8) * 2);

    auto load_chunk = [&](int c) {
        const int k0 = c * 32;
        const uint32_t st = sb + (uint32_t)(c & 1) * STAGE_BYTES;
#pragma unroll
        for (int i = 0; i < 8; i++) {
            int v = tid + i * 256;
            int mat = v >> 9, r = (v >> 2) & 127, c16 = v & 3;
            uint32_t dst = st + mat * MAT_BYTES + r * 112 + c16 * 16;
            const __nv_bfloat16* srcp;
            int sz = 16;
            if (mat == 0)      srcp = Ah + (size_t)(row0 + r) * K + k0 + c16 * 8;
            else if (mat == 1) srcp = Al + (size_t)(row0 + r) * K + k0 + c16 * 8;
            else {
                int n = col0 + r;
                int nn = (n < N) ? n : 0;
                if (n >= N) sz = 0;
                srcp = (mat == 2 ? Bth : Btl) + (size_t)nn * K + k0 + c16 * 8;
            }
            asm volatile("cp.async.cg.shared.global [%0], [%1], 16, %2;"
                         :: "r"(dst), "l"(srcp), "r"(sz));
        }
        asm volatile("cp.async.commit_group;" ::: "memory");
    };

    load_chunk(0);

    for (int c = 0; c < nchunk; c++) {
        if (c + 1 < nchunk) {
            load_chunk(c + 1);
            asm volatile("cp.async.wait_group 1;" ::: "memory");
        } else {
            asm volatile("cp.async.wait_group 0;" ::: "memory");
        }
        __syncthreads();

        const uint32_t st = sb + (uint32_t)(c & 1) * STAGE_BYTES;
#pragma unroll
        for (int ks = 0; ks < 2; ks++) {
            uint32_t ah[4][4], al[4][4];
#pragma unroll
            for (int mi = 0; mi < 4; mi++) {
                uint32_t addr = st + a_off + mi * (16 * 112) + ks * 32;
                asm volatile("ldmatrix.sync.aligned.m8n8.x4.shared.b16 {%0,%1,%2,%3}, [%4];"
                             : "=r"(ah[mi][0]), "=r"(ah[mi][1]), "=r"(ah[mi][2]), "=r"(ah[mi][3])
                             : "r"(addr));
                asm volatile("ldmatrix.sync.aligned.m8n8.x4.shared.b16 {%0,%1,%2,%3}, [%4];"
                             : "=r"(al[mi][0]), "=r"(al[mi][1]), "=r"(al[mi][2]), "=r"(al[mi][3])
                             : "r"(addr + MAT_BYTES));
            }
#pragma unroll
            for (int b2 = 0; b2 < 2; b2++) {
                uint32_t bh[4], bl[4];
                uint32_t baddr = st + 2 * MAT_BYTES + b_off + b2 * (16 * 112) + ks * 32;
                asm volatile("ldmatrix.sync.aligned.m8n8.x4.shared.b16 {%0,%1,%2,%3}, [%4];"
                             : "=r"(bh[0]), "=r"(bh[1]), "=r"(bh[2]), "=r"(bh[3]) : "r"(baddr));
                asm volatile("ldmatrix.sync.aligned.m8n8.x4.shared.b16 {%0,%1,%2,%3}, [%4];"
                             : "=r"(bl[0]), "=r"(bl[1]), "=r"(bl[2]), "=r"(bl[3])
                             : "r"(baddr + MAT_BYTES));
#pragma unroll
                for (int p = 0; p < 3; p++) {
#pragma unroll
                    for (int mi = 0; mi < 4; mi++) {
#pragma unroll
                        for (int hf = 0; hf < 2; hf++) {
                            const int nt = b2 * 2 + hf;
                            const uint32_t* A_ = (p == 2) ? al[mi] : ah[mi];
                            const uint32_t* B_ = (p == 1) ? bl : bh;
                            asm volatile(
                                "mma.sync.aligned.m16n8k16.row.col.f32.bf16.bf16.f32 "
                                "{%0,%1,%2,%3},{%4,%5,%6,%7},{%8,%9},{%0,%1,%2,%3};"
                                : "+f"(acc[mi][nt][0]), "+f"(acc[mi][nt][1]),
                                  "+f"(acc[mi][nt][2]), "+f"(acc[mi][nt][3])
                                : "r"(A_[0]), "r"(A_[1]), "r"(A_[2]), "r"(A_[3]),
                                  "r"(B_[hf * 2]), "r"(B_[hf * 2 + 1]));
                        }
                    }
                }
            }
        }
        __syncthreads();
    }

    const int g = lane >> 2, c2 = lane & 3;
#pragma unroll
    for (int mi = 0; mi < 4; mi++) {
        const int r = row0 + warp_m * 64 + mi * 16 + g;
#pragma unroll
        for (int nt = 0; nt < 4; nt++) {
            const int col = col0 + warp_n * 32 + nt * 8 + c2 * 2;
            if (col < N) {
                *(float2*)(C + (size_t)r * N + col)       = make_float2(acc[mi][nt][0], acc[mi][nt][1]);
                *(float2*)(C + (size_t)(r + 8) * N + col) = make_float2(acc[mi][nt][2], acc[mi][nt][3]);
            }
        }
    }
}

// ---------------- compressed tokens ----------------
__global__ void compress_kernel(const float* __restrict__ wck,
                                const float* __restrict__ wcv,
                                const float* __restrict__ pe)
{
    const int m = blockIdx.x, h = blockIdx.y, d = threadIdx.x;  // 64 threads
    float a = 0.f, b = 0.f;
    for (int t = 0; t < 64; t++) {
        const float wk = wck[h * 64 + t];
        const float wv = wcv[h * 64 + t];
        const int row = m * 64 + t;
        a = fmaf(g_kvg[row * 352 + h * 64 + d] + pe[(h * 64 + t) * 64 + d], wk, a);
        b = fmaf(g_kvg[row * 352 + 128 + h * 64 + d], wv, b);
    }
    g_ck[(m * 2 + h) * 64 + d] = a;
    g_cv[(m * 2 + h) * 64 + d] = b;
}

// ---------------- compressed attention + top-k, 4 tokens per CTA ----------------
// grid (ntok/4, 2), 512 threads: token tq = tid>>7, local ltid = tid&127.
__global__ void __launch_bounds__(512) comp_attn_kernel(int ntok)
{
    const int n0 = blockIdx.x * 4, h = blockIdx.y;
    const int tid = threadIdx.x;
    const int tq = tid >> 7, ltid = tid & 127;
    const int M = ntok >> 6;
    __shared__ float  sq[4096];               // [token][16][64], prescaled
    __shared__ float2 ckp[32 * 33];           // [d2][m] pairs, padded
    __shared__ float  scv[MMAX * 64];
    __shared__ float  lg[4 * 512];            // [token][16][32]
    __shared__ float  ssum[4 * 32];

    for (int i = tid; i < 4096; i += 512) {
        int q = i >> 10;
        sq[i] = g_q[(n0 + q) * 2048 + h * 1024 + (i & 1023)] * 0.125f;
    }
    for (int i = tid; i < M * 32; i += 512) {
        int m = i >> 5, d2 = i & 31;
        ckp[d2 * 33 + m] = *(const float2*)&g_ck[(m * 2 + h) * 64 + 2 * d2];
    }
    for (int i = tid; i < M * 64; i += 512)
        scv[i] = g_cv[((i >> 6) * 2 + h) * 64 + (i & 63)];
    __syncthreads();

    const int n = n0 + tq;
    const int mvis = (n >= 63) ? (((n - 63) >> 6) + 1) : 0;

    // QK: 512 logits/token, 4 per thread
#pragma unroll
    for (int i = 0; i < 4; i++) {
        int e = ltid + i * 128;
        int g = e >> 5, m = e & 31;
        unsigned long long acc = 0ull;
#pragma unroll
        for (int d2 = 0; d2 < 32; d2++) {
            unsigned long long qp = pk2f2(*(const float2*)&sq[tq * 1024 + g * 64 + 2 * d2]);
            acc = fma2(qp, pk2f2(ckp[d2 * 33 + m]), acc);
        }
        float x, y; upk2(acc, x, y);
        lg[tq * 512 + g * 32 + m] = x + y;
    }
    __syncthreads();

    if (ltid < 16) {
        float* row = lg + tq * 512 + ltid * 32;
        if (mvis == 0) {
            for (int m = 0; m < M; m++) row[m] = 0.f;
        } else {
            float mx = -INFINITY;
            for (int m = 0; m < mvis; m++) mx = fmaxf(mx, row[m]);
            float s = 0.f;
            for (int m = 0; m < mvis; m++) {
                float p = __expf(row[m] - mx);
                row[m] = p; s += p;
            }
            const float inv = 1.f / s;
            for (int m = 0; m < mvis; m++) row[m] *= inv;
            for (int m = mvis; m < M; m++) row[m] = 0.f;
        }
    }
    __syncthreads();

    // PV: 512 d-pairs/token, 4 per thread
#pragma unroll
    for (int i = 0; i < 4; i++) {
        int e2 = ltid + i * 128;
        int g = e2 >> 5, d2 = e2 & 31;
        unsigned long long acc = 0ull;
        for (int m = 0; m < mvis; m++) {
            float p = lg[tq * 512 + g * 32 + m];
            acc = fma2(pk2(p, p), pk2f2(*(const float2*)&scv[m * 64 + 2 * d2]), acc);
        }
        float x, y; upk2(acc, x, y);
        *(float2*)&g_comp[n * 2048 + h * 1024 + g * 64 + 2 * d2] = make_float2(x, y);
    }

    if (ltid < 32) {
        float s = 0.f;
        if (ltid < M)
            for (int g = 0; g < 16; g++) s += lg[tq * 512 + g * 32 + ltid];
        ssum[tq * 32 + ltid] = s;
    }
    __syncthreads();

    if (ltid == 0) {
        const int qblk = n >> 6;
        unsigned sel = 0;
        if (qblk + 1 <= 16) {
            sel = (1u << (qblk + 1)) - 1u;
        } else {
            float sc[32];
            for (int m = 0; m < 32; m++) {
                if (m > qblk)                                  sc[m] = -INFINITY;
                else if (m == 0 || m == qblk || m == qblk - 1) sc[m] = INFINITY;
                else                                           sc[m] = ssum[tq * 32 + m];
            }
            for (int t = 0; t < 16; t++) {
                int best = 0; float bv = -INFINITY;
                for (int m = 0; m < 32; m++) {
                    if ((sel >> m) & 1u) continue;
                    if (sc[m] > bv) { bv = sc[m]; best = m; }
                }
                sel |= 1u << best;
            }
        }
        g_sel[n * 2 + h] = sel;
    }
}

// ---------------- main attention: 4 tokens per CTA, f32x2 packed ----------------
// 256 threads. Rows r = token*16 + head (64 rows). Writes split-bf16 fused output.
#define ATTN_SMEM 102144
__global__ void __launch_bounds__(256) main_attn_kernel(int ntok)
{
    extern __shared__ char dsm[];
    float*  sq  = (float*)dsm;                    // [64][64] prescaled Q
    float*  lg  = (float*)(dsm + 16384);          // [64][64] logits
    float2* pp  = (float2*)(dsm + 32768);         // [64][64] {p_s, p_w}
    float2* skp = (float2*)(dsm + 65536);         // [32][65] K d-pairs
    float*  sv  = (float*)(dsm + 82176);          // [64][64]
    float*  pm  = (float*)(dsm + 98560);          // [512] partials
    float*  hmm = (float*)(dsm + 100608);         // [2][64]
    float*  hll = (float*)(dsm + 101120);
    float*  hrr = (float*)(dsm + 101632);

    const int n0 = blockIdx.x * 4, h = blockIdx.y;
    const int tid = threadIdx.x;

    for (int i = tid; i < 4096; i += 256) {
        int r = i >> 6;
        sq[i] = g_q[(n0 + (r >> 4)) * 2048 + h * 1024 + (r & 15) * 64 + (i & 63)] * 0.125f;
    }
    if (tid < 128) { hmm[tid] = -INFINITY; hll[tid] = 0.f; }

    const unsigned sel0 = g_sel[n0 * 2 + h],       sel1 = g_sel[(n0 + 1) * 2 + h],
                   sel2 = g_sel[(n0 + 2) * 2 + h], sel3 = g_sel[(n0 + 3) * 2 + h];
    const unsigned selU = sel0 | sel1 | sel2 | sel3;
    const int qblk = n0 >> 6;

    const int rq = tid >> 4;             // head (row base within token)
    const int d4 = (tid & 15) * 4;       // d base
    unsigned long long acc2[4][4] = {};  // [token][d_off] = {sparse, window}

    __syncthreads();

    for (int c = 0; c <= qblk; c++) {
        const int base = n0 - c * 64;                 // n_q - c*64 = base + q
        const bool anyw = (base - 512) <= 63;         // window overlap (min token)
        if (!((selU >> c) & 1u) && !anyw) continue;
        const int jnU = min(63, base + 3);

        for (int i = tid; i < 2048; i += 256) {
            int j = i >> 5, d2 = i & 31;
            skp[d2 * 65 + j] = (j <= jnU)
                ? *(const float2*)&g_kvg[(c * 64 + j) * 352 + h * 64 + 2 * d2]
                : make_float2(0.f, 0.f);
        }
        for (int i = tid; i < 4096; i += 256) {
            int j = i >> 6;
            sv[i] = (j <= jnU) ? g_kvg[(c * 64 + j) * 352 + h * 64 + 128 + (i & 63)] : 0.f;
        }
        __syncthreads();

        // QK: 4096 logits, 16 per thread
#pragma unroll
        for (int i = 0; i < 16; i++) {
            int e = tid + i * 256;
            int r = e >> 6, j = e & 63;
            unsigned long long a = 0ull;
#pragma unroll
            for (int d2 = 0; d2 < 32; d2++)
                a = fma2(pk2f2(*(const float2*)&sq[r * 64 + 2 * d2]),
                         pk2f2(skp[d2 * 65 + j]), a);
            float x, y; upk2(a, x, y);
            lg[e] = x + y;
        }
        __syncthreads();

        // segmented max: thread does (sparse, window) for (r = tid>>2, seg = tid&3)
        {
            const int r = tid >> 2, seg = tid & 3;
            const int q = r >> 4;
            const int jn = min(63, base + q);
            const unsigned selq = (q == 0) ? sel0 : (q == 1) ? sel1 : (q == 2) ? sel2 : sel3;
            const int jw0 = base + q - 512;
            float ms = -INFINITY;
            if ((selq >> c) & 1u) {
                const int hi = min(seg * 16 + 15, jn);
                for (int j = seg * 16; j <= hi; j++) ms = fmaxf(ms, lg[r * 64 + j]);
            }
            pm[tid] = ms;
            float mw = -INFINITY;
            if (jw0 <= 63) {
                const int lo = max(seg * 16, jw0);
                const int hi = min(seg * 16 + 15, jn);
                for (int j = lo; j <= hi; j++) mw = fmaxf(mw, lg[r * 64 + j]);
            }
            pm[256 + tid] = mw;
        }
        __syncthreads();
        if (tid < 128) {
            const int br = tid >> 6, r = tid & 63;
            const float* p = pm + br * 256 + r * 4;
            const float cm = fmaxf(fmaxf(p[0], p[1]), fmaxf(p[2], p[3]));
            const float om = hmm[br * 64 + r];
            const float nm = fmaxf(om, cm);
            hmm[br * 64 + r] = nm;
            hrr[br * 64 + r] = (cm == -INFINITY) ? 1.f : __expf(om - nm);
        }
        __syncthreads();

        // exp -> pp
#pragma unroll
        for (int i = 0; i < 16; i++) {
            int e = tid + i * 256;
            int r = e >> 6, j = e & 63;
            const int q = r >> 4;
            const unsigned selq = (q == 0) ? sel0 : (q == 1) ? sel1 : (q == 2) ? sel2 : sel3;
            const int jn = base + q;
            const int jw0 = base + q - 512;
            const float l = lg[e];
            const bool jc = (j <= jn);
            float es = (jc && ((selq >> c) & 1u)) ? __expf(l - hmm[r])      : 0.f;
            float ew = (jc && j >= jw0)           ? __expf(l - hmm[64 + r]) : 0.f;
            pp[r * 64 + j] = make_float2(es, ew);
        }
        __syncthreads();

        // segmented sum
        {
            const int r = tid >> 2, seg = tid & 3;
            float ss = 0.f, sw = 0.f;
            for (int j = seg * 16; j < seg * 16 + 16; j++) {
                float2 v = pp[r * 64 + j];
                ss += v.x; sw += v.y;
            }
            pm[tid] = ss; pm[256 + tid] = sw;
        }
        __syncthreads();
        if (tid < 128) {
            const int br = tid >> 6, r = tid & 63;
            const float* p = pm + br * 256 + r * 4;
            hll[br * 64 + r] = hll[br * 64 + r] * hrr[br * 64 + r]
                             + (p[0] + p[1]) + (p[2] + p[3]);
        }

        // PV: thread owns (head rq, d4..d4+3) x 4 tokens
#pragma unroll
        for (int m = 0; m < 4; m++) {
            const int r = m * 16 + rq;
            const unsigned long long sc = pk2(hrr[r], hrr[64 + r]);
#pragma unroll
            for (int dd = 0; dd < 4; dd++) acc2[m][dd] = mul2(acc2[m][dd], sc);
        }
        for (int j = 0; j <= jnU; j++) {
            const float4 v4 = *(const float4*)&sv[j * 64 + d4];
            const unsigned long long v0 = pk2(v4.x, v4.x), v1 = pk2(v4.y, v4.y),
                                     v2 = pk2(v4.z, v4.z), v3 = pk2(v4.w, v4.w);
#pragma unroll
            for (int m = 0; m < 4; m++) {
                const unsigned long long p = pk2f2(pp[(m * 16 + rq) * 64 + j]);
                acc2[m][0] = fma2(p, v0, acc2[m][0]);
                acc2[m][1] = fma2(p, v1, acc2[m][1]);
                acc2[m][2] = fma2(p, v2, acc2[m][2]);
                acc2[m][3] = fma2(p, v3, acc2[m][3]);
            }
        }
        __syncthreads();
    }

    // gated fusion -> split bf16 output
#pragma unroll
    for (int m = 0; m < 4; m++) {
        const int r = m * 16 + rq;
        const int nq = n0 + m;
        const int hq = h * 16 + rq;
        const float gl0 = g_kvg[nq * 352 + 256 + hq * 3 + 0];
        const float gl1 = g_kvg[nq * 352 + 256 + hq * 3 + 1];
        const float gl2 = g_kvg[nq * 352 + 256 + hq * 3 + 2];
        const float g0 = 1.f / (1.f + __expf(-gl0));
        const float g1 = 1.f / (1.f + __expf(-gl1));
        const float g2 = 1.f / (1.f + __expf(-gl2));
        const float inv_s = 1.f / hll[r];
        const float inv_w = 1.f / hll[64 + r];
#pragma unroll
        for (int dd = 0; dd < 4; dd++) {
            float ax, ay; upk2(acc2[m][dd], ax, ay);
            const int oi = nq * 2048 + h * 1024 + rq * 64 + d4 + dd;
            const float o = g0 * g_comp[oi] + g1 * (ax * inv_s) + g2 * (ay * inv_w);
            const __nv_bfloat16 hi = __float2bfloat16(o);
            g_fh[oi] = hi;
            g_fl[oi] = __float2bfloat16(o - __bfloat162float(hi));
        }
    }
}

// ---------------- launch ----------------
extern "C" void kernel_launch(void* const* d_in, const int* in_sizes, int n_in,
                              void* d_out, int out_size)
{
    const float* x   = (const float*)d_in[0];
    const float* Wq  = (const float*)d_in[2];
    const float* Wk  = (const float*)d_in[3];
    const float* Wv  = (const float*)d_in[4];
    const float* Wo  = (const float*)d_in[5];
    const float* Wg  = (const float*)d_in[6];
    const float* wck = (const float*)d_in[7];
    const float* wcv = (const float*)d_in[8];
    const float* pe  = (const float*)d_in[9];
    float* out = (float*)d_out;

    const int ntok = in_sizes[0] / 2048;     // T = 2048
    const int M = ntok / 64;

    float *q, *kvg;
    cudaGetSymbolAddress((void**)&q,   g_q);
    cudaGetSymbolAddress((void**)&kvg, g_kvg);

    __nv_bfloat16 *xh, *xl, *fh, *fl, *wqh, *wql, *woh, *wol, *wkvgh, *wkvgl;
    cudaGetSymbolAddress((void**)&xh, g_xh);     cudaGetSymbolAddress((void**)&xl, g_xl);
    cudaGetSymbolAddress((void**)&fh, g_fh);     cudaGetSymbolAddress((void**)&fl, g_fl);
    cudaGetSymbolAddress((void**)&wqh, g_wqt_h); cudaGetSymbolAddress((void**)&wql, g_wqt_l);
    cudaGetSymbolAddress((void**)&woh, g_wot_h); cudaGetSymbolAddress((void**)&wol, g_wot_l);
    cudaGetSymbolAddress((void**)&wkvgh, g_wkvgt_h);
    cudaGetSymbolAddress((void**)&wkvgl, g_wkvgt_l);

    const int SMEM_GEMM = 2 * STAGE_BYTES;   // 114688
    cudaFuncSetAttribute(mma_gemm, cudaFuncAttributeMaxDynamicSharedMemorySize, SMEM_GEMM);
    cudaFuncSetAttribute(main_attn_kernel, cudaFuncAttributeMaxDynamicSharedMemorySize, ATTN_SMEM);

    const int tot = ntok * 2048;
    dim3 tb(32, 8);

    split_fp32<<<(tot + 255) / 256, 256>>>(x, xh, xl, tot);
    transpose_split<<<dim3(64, 64), tb>>>(Wq, wqh, wql, 2048, 2048);
    transpose_split<<<dim3(4,  64), tb>>>(Wk, wkvgh,              wkvgl,              2048, 128);
    transpose_split<<<dim3(4,  64), tb>>>(Wv, wkvgh + 128 * 2048, wkvgl + 128 * 2048, 2048, 128);
    transpose_split<<<dim3(3,  64), tb>>>(Wg, wkvgh + 256 * 2048, wkvgl + 256 * 2048, 2048, 96);
    transpose_split<<<dim3(64, 64), tb>>>(Wo, woh, wol, 2048, 2048);

    mma_gemm<<<dim3(16, ntok / 128), 256, SMEM_GEMM>>>(xh, xl, wqh, wql, q, ntok, 2048, 2048);
    mma_gemm<<<dim3(3,  ntok / 128), 256, SMEM_GEMM>>>(xh, xl, wkvgh, wkvgl, kvg, ntok, 352, 2048);

    compress_kernel<<<dim3(M, 2), 64>>>(wck, wcv, pe);
    comp_attn_kernel<<<dim3(ntok / 4, 2), 512>>>(ntok);
    main_attn_kernel<<<dim3(ntok / 4, 2), 256, ATTN_SMEM>>>(ntok);

    mma_gemm<<<dim3(16, ntok / 128), 256, SMEM_GEMM>>>(fh, fl, woh, wol, out, ntok, 2048, 2048);
}